// round 15
// baseline (speedup 1.0000x reference)
#include <cuda_runtime.h>
#include <math.h>

#define NW 10
#define NP 5                  // wire pairs
#define NQ 4                  // quantities per pair: cc, cs, sc, ss
#define NSAMP 4096
#define TMC 128               // X rows per CTA (8 warps x 16 rows)
#define TNC 64                // Y cols per CTA (lane, lane+32)

typedef unsigned long long u64;

// out[x, y] = prod_i cos^2((X[x,i] - Y[y,i]) / 2)
// (unitary invariance: shared-params RZ/CNOT circuit cancels in <psi_x|psi_y>;
//  product-state overlap factorizes per qubit. Wire-pair expansion:
//  (ci*cyi + si*syi)(cj*cyj + sj*syj) = cc*CC + cs*CS + sc*SC + ss*SS.)

// global pair-product tables (device-code references ONLY)
__device__ float g_Xp[NP * NQ][NSAMP];      // x side: (p,q)-major rows
__device__ float g_Yp[NSAMP][NP * NQ];      // y side: sample-major, 20 floats/row

__device__ __forceinline__ u64 dup2(float a) {
    u64 r; asm("mov.b64 %0, {%1, %1};" : "=l"(r) : "f"(a)); return r;
}
__device__ __forceinline__ u64 mul2(u64 a, u64 b) {
    u64 r; asm("mul.rn.f32x2 %0, %1, %2;" : "=l"(r) : "l"(a), "l"(b)); return r;
}
__device__ __forceinline__ u64 fma2(u64 a, u64 b, u64 c) {
    u64 r; asm("fma.rn.f32x2 %0, %1, %2, %3;" : "=l"(r) : "l"(a), "l"(b), "l"(c)); return r;
}
__device__ __forceinline__ void unpk(u64 v, float& lo, float& hi) {
    asm("mov.b64 {%0, %1}, %2;" : "=f"(lo), "=f"(hi) : "l"(v));
}

// one thread per (pair, sample): 20480 threads
__global__ void tab_kernel(const float* __restrict__ X, const float* __restrict__ Y) {
    const int t = blockIdx.x * 256 + threadIdx.x;
    const int p = t >> 12;          // 0..4
    const int s = t & 4095;
    float si, ci, sj, cj;
    __sincosf(0.5f * X[s * NW + 2 * p],     &si, &ci);
    __sincosf(0.5f * X[s * NW + 2 * p + 1], &sj, &cj);
    g_Xp[p * NQ + 0][s] = ci * cj;
    g_Xp[p * NQ + 1][s] = ci * sj;
    g_Xp[p * NQ + 2][s] = si * cj;
    g_Xp[p * NQ + 3][s] = si * sj;
    __sincosf(0.5f * Y[s * NW + 2 * p],     &si, &ci);
    __sincosf(0.5f * Y[s * NW + 2 * p + 1], &sj, &cj);
    g_Yp[s][p * NQ + 0] = ci * cj;
    g_Yp[s][p * NQ + 1] = ci * sj;
    g_Yp[s][p * NQ + 2] = si * cj;
    g_Yp[s][p * NQ + 3] = si * sj;
}

#define XCH (NP * NQ * TMC / 4)    // 640 float4 chunks
#define YCH (TNC * NP)             // 320 float4 chunks (5 per col row)

__global__ void __launch_bounds__(256, 3)
qk_kernel(float* __restrict__ out) {
    __shared__ __align__(16) float sx[NP * NQ][TMC];     // 10 KB
    __shared__ __align__(16) float sy[TNC][NP * NQ];     // 5 KB (80B rows, conflict-free)

    const int tid = threadIdx.x;
    const int bn = blockIdx.x * TNC;    // Y cols
    const int bm = blockIdx.y * TMC;    // X rows

    // prologue: pure coalesced float4 copies of precomputed tables
    {
        float4* dx = (float4*)sx;
        float4* dy = (float4*)sy;
        const float* gx = &g_Xp[0][0];
        for (int c = tid; c < XCH + YCH; c += 256) {
            if (c < XCH) {
                int pq = c >> 5, off = c & 31;   // 32 chunks per (p,q) row
                dx[c] = ((const float4*)(gx + pq * NSAMP + bm))[off];
            } else {
                int c2 = c - XCH;                // 5 chunks per col row
                int col = c2 / 5, j = c2 - 5 * col;
                dy[col * 5 + j] = ((const float4*)(&g_Yp[bn + col][0]))[j];
            }
        }
    }
    __syncthreads();

    const int warp = tid >> 5;
    const int lane = tid & 31;
    const int r0 = warp * 16;           // warp-uniform 16-row block
    // cols: bn + lane  and  bn + lane + 32

    u64 acc[8][2];                      // [row-pack][col]

#pragma unroll
    for (int p = 0; p < NP; ++p) {
        // y side: one conflict-free LDS.128 per col, dup-packed (resident per p)
        float4 ya = *(const float4*)&sy[lane][p * NQ];
        float4 yb = *(const float4*)&sy[lane + 32][p * NQ];
        u64 y0[NQ] = {dup2(ya.x), dup2(ya.y), dup2(ya.z), dup2(ya.w)};
        u64 y1[NQ] = {dup2(yb.x), dup2(yb.y), dup2(yb.z), dup2(yb.w)};

        // x side: 4 quarters of 4 rows; warp-uniform broadcast LDS.128
        // each .128 = 2 natural f32x2 row-pair packs
#pragma unroll
        for (int h = 0; h < 4; ++h) {
            u64 xq[NQ][2];
#pragma unroll
            for (int q = 0; q < NQ; ++q) {
                ulonglong2 v = *(const ulonglong2*)&sx[p * NQ + q][r0 + 4 * h];
                xq[q][0] = v.x; xq[q][1] = v.y;
            }
#pragma unroll
            for (int k = 0; k < 2; ++k) {
                const int kk = 2 * h + k;
                u64 t0 = mul2(xq[0][k], y0[0]);
                t0 = fma2(xq[1][k], y0[1], t0);
                t0 = fma2(xq[2][k], y0[2], t0);
                t0 = fma2(xq[3][k], y0[3], t0);
                u64 t1 = mul2(xq[0][k], y1[0]);
                t1 = fma2(xq[1][k], y1[1], t1);
                t1 = fma2(xq[2][k], y1[2], t1);
                t1 = fma2(xq[3][k], y1[3], t1);
                if (p == 0) { acc[kk][0] = t0; acc[kk][1] = t1; }
                else        { acc[kk][0] = mul2(acc[kk][0], t0);
                              acc[kk][1] = mul2(acc[kk][1], t1); }
            }
        }
    }

    // epilogue: square, unpack row-pair packs, coalesced scalar stores
#pragma unroll
    for (int kk = 0; kk < 8; ++kk) {
        const int row = bm + r0 + 2 * kk;
#pragma unroll
        for (int c = 0; c < 2; ++c) {
            u64 sq = mul2(acc[kk][c], acc[kk][c]);
            float lo, hi;
            unpk(sq, lo, hi);
            const int col = bn + lane + 32 * c;
            out[(size_t)row * NSAMP + col] = lo;
            out[(size_t)(row + 1) * NSAMP + col] = hi;
        }
    }
}

extern "C" void kernel_launch(void* const* d_in, const int* in_sizes, int n_in,
                              void* d_out, int out_size) {
    const float* X = (const float*)d_in[0];      // (4096, 10)
    const float* Y = (const float*)d_in[1];      // (4096, 10)
    // d_in[2] (params) provably does not affect the output (unitary invariance)
    float* out = (float*)d_out;                  // (4096, 4096)

    tab_kernel<<<NP * NSAMP / 256, 256>>>(X, Y);   // 80 CTAs

    dim3 grid(NSAMP / TNC, NSAMP / TMC);           // (64, 32)
    qk_kernel<<<grid, 256>>>(out);
}

// round 16
// speedup vs baseline: 1.0945x; 1.0945x over previous
#include <cuda_runtime.h>
#include <math.h>

#define NW 10
#define NP 5                  // wire pairs
#define NSAMP 4096
#define CTA_R 32              // X rows per CTA (8 warps x 4 rows)
#define CTA_C 64              // Y cols per CTA (lane, lane+32)

typedef unsigned long long u64;

// out[x, y] = prod_i cos^2((X[x,i] - Y[y,i]) / 2)
// (unitary invariance: shared-params RZ/CNOT circuit cancels in <psi_x|psi_y>;
//  product-state overlap factorizes per qubit. Wire-pair expansion:
//  (ci*cyi + si*syi)(cj*cyj + sj*syj) = cc*CC + cs*CS + sc*SC + ss*SS.)

__device__ __forceinline__ u64 dup2(float a) {
    u64 r; asm("mov.b64 %0, {%1, %1};" : "=l"(r) : "f"(a)); return r;
}
__device__ __forceinline__ u64 mul2(u64 a, u64 b) {
    u64 r; asm("mul.rn.f32x2 %0, %1, %2;" : "=l"(r) : "l"(a), "l"(b)); return r;
}
__device__ __forceinline__ u64 fma2(u64 a, u64 b, u64 c) {
    u64 r; asm("fma.rn.f32x2 %0, %1, %2, %3;" : "=l"(r) : "l"(a), "l"(b), "l"(c)); return r;
}
__device__ __forceinline__ void unpk(u64 v, float& lo, float& hi) {
    asm("mov.b64 {%0, %1}, %2;" : "=f"(lo), "=f"(hi) : "l"(v));
}

__global__ void __launch_bounds__(256, 6)
qk_kernel(const float* __restrict__ X, const float* __restrict__ Y,
          float* __restrict__ out) {
    __shared__ __align__(16) float sx[NP][4][CTA_R];   // 2.5 KB
    __shared__ __align__(16) float sy[CTA_C][NP * 4];  // 5 KB (80B rows, conflict-free)

    const int tid = threadIdx.x;
    const int bn = blockIdx.x * CTA_C;    // Y cols
    const int bm = blockIdx.y * CTA_R;    // X rows

    // fused prologue: compute pair-product tables in-CTA (MUFU only, no global tables)
    for (int it = tid; it < (CTA_R + CTA_C) * NP; it += 256) {
        if (it < CTA_R * NP) {
            int p = it >> 5, row = it & (CTA_R - 1);
            float2 a = *(const float2*)(X + (size_t)(bm + row) * NW + 2 * p);
            float si, ci, sj, cj;
            __sincosf(0.5f * a.x, &si, &ci);
            __sincosf(0.5f * a.y, &sj, &cj);
            sx[p][0][row] = ci * cj;
            sx[p][1][row] = ci * sj;
            sx[p][2][row] = si * cj;
            sx[p][3][row] = si * sj;
        } else {
            int it2 = it - CTA_R * NP;
            int p = it2 >> 6, col = it2 & (CTA_C - 1);
            float2 a = *(const float2*)(Y + (size_t)(bn + col) * NW + 2 * p);
            float si, ci, sj, cj;
            __sincosf(0.5f * a.x, &si, &ci);
            __sincosf(0.5f * a.y, &sj, &cj);
            sy[col][4 * p + 0] = ci * cj;
            sy[col][4 * p + 1] = ci * sj;
            sy[col][4 * p + 2] = si * cj;
            sy[col][4 * p + 3] = si * sj;
        }
    }
    __syncthreads();

    const int warp = tid >> 5;
    const int lane = tid & 31;
    const int r0 = warp * 4;              // warp-uniform 4-row block
    // cols: bn + lane  and  bn + lane + 32

    u64 acc[2][2];                        // [rowpack][colhalf]

#pragma unroll
    for (int p = 0; p < NP; ++p) {
        // x side: 4 quantities x 4 rows each -> one broadcast LDS.128 per q;
        // .x = rows (r0, r0+1) pack, .y = rows (r0+2, r0+3) pack
        ulonglong2 x0 = *(const ulonglong2*)&sx[p][0][r0];
        ulonglong2 x1 = *(const ulonglong2*)&sx[p][1][r0];
        ulonglong2 x2 = *(const ulonglong2*)&sx[p][2][r0];
        ulonglong2 x3 = *(const ulonglong2*)&sx[p][3][r0];
#pragma unroll
        for (int c = 0; c < 2; ++c) {
            // y side: one conflict-free LDS.128 (stride-20 rows), dup-packed
            float4 yv = *(const float4*)&sy[lane + 32 * c][4 * p];
            u64 y0 = dup2(yv.x), y1 = dup2(yv.y), y2 = dup2(yv.z), y3 = dup2(yv.w);
            u64 t0 = mul2(x0.x, y0);
            t0 = fma2(x1.x, y1, t0);
            t0 = fma2(x2.x, y2, t0);
            t0 = fma2(x3.x, y3, t0);
            u64 t1 = mul2(x0.y, y0);
            t1 = fma2(x1.y, y1, t1);
            t1 = fma2(x2.y, y2, t1);
            t1 = fma2(x3.y, y3, t1);
            if (p == 0) { acc[0][c] = t0; acc[1][c] = t1; }
            else        { acc[0][c] = mul2(acc[0][c], t0);
                          acc[1][c] = mul2(acc[1][c], t1); }
        }
    }

    // epilogue: square, unpack row-pair packs, coalesced scalar stores
#pragma unroll
    for (int k = 0; k < 2; ++k) {
        const int row = bm + r0 + 2 * k;
#pragma unroll
        for (int c = 0; c < 2; ++c) {
            u64 sq = mul2(acc[k][c], acc[k][c]);
            float lo, hi;
            unpk(sq, lo, hi);
            const int col = bn + lane + 32 * c;
            out[(size_t)row * NSAMP + col] = lo;
            out[(size_t)(row + 1) * NSAMP + col] = hi;
        }
    }
}

extern "C" void kernel_launch(void* const* d_in, const int* in_sizes, int n_in,
                              void* d_out, int out_size) {
    const float* X = (const float*)d_in[0];      // (4096, 10)
    const float* Y = (const float*)d_in[1];      // (4096, 10)
    // d_in[2] (params) provably does not affect the output (unitary invariance)
    float* out = (float*)d_out;                  // (4096, 4096)

    dim3 grid(NSAMP / CTA_C, NSAMP / CTA_R);     // (64, 128) = 8192 CTAs
    qk_kernel<<<grid, 256>>>(X, Y, out);
}

// round 17
// speedup vs baseline: 1.1649x; 1.0643x over previous
#include <cuda_runtime.h>
#include <math.h>

#define NW 10
#define NP 5                  // wire pairs
#define NQ 4                  // quantities per pair: cc, cs, sc, ss
#define NSAMP 4096
#define CTA_R 32              // X rows per CTA (8 warps x 4 rows)
#define CTA_C 128             // Y cols per CTA (thread owns 4 consecutive cols)

typedef unsigned long long u64;

// out[x, y] = prod_i cos^2((X[x,i] - Y[y,i]) / 2)
// (unitary invariance: shared-params RZ/CNOT circuit cancels in <psi_x|psi_y>;
//  product-state overlap factorizes per qubit. Wire-pair expansion:
//  (ci*cyi + si*syi)(cj*cyj + sj*syj) = cc*CC + cs*CS + sc*SC + ss*SS.)

__device__ __forceinline__ u64 dup2(float a) {
    u64 r; asm("mov.b64 %0, {%1, %1};" : "=l"(r) : "f"(a)); return r;
}
__device__ __forceinline__ u64 mul2(u64 a, u64 b) {
    u64 r; asm("mul.rn.f32x2 %0, %1, %2;" : "=l"(r) : "l"(a), "l"(b)); return r;
}
__device__ __forceinline__ u64 fma2(u64 a, u64 b, u64 c) {
    u64 r; asm("fma.rn.f32x2 %0, %1, %2, %3;" : "=l"(r) : "l"(a), "l"(b), "l"(c)); return r;
}

__global__ void __launch_bounds__(256, 4)
qk_kernel(const float* __restrict__ X, const float* __restrict__ Y,
          float* __restrict__ out) {
    __shared__ __align__(16) float sx[NP][NQ][CTA_R];   // 2.5 KB
    __shared__ __align__(16) float sy[NP][NQ][CTA_C];   // 10 KB

    const int tid = threadIdx.x;
    const int bn = blockIdx.x * CTA_C;    // Y cols
    const int bm = blockIdx.y * CTA_R;    // X rows

    // fused prologue: in-CTA pair-product tables (MUFU only)
    for (int it = tid; it < NP * (CTA_R + CTA_C); it += 256) {
        if (it < NP * CTA_R) {
            int p = it >> 5, row = it & (CTA_R - 1);
            float2 a = *(const float2*)(X + (size_t)(bm + row) * NW + 2 * p);
            float si, ci, sj, cj;
            __sincosf(0.5f * a.x, &si, &ci);
            __sincosf(0.5f * a.y, &sj, &cj);
            sx[p][0][row] = ci * cj;
            sx[p][1][row] = ci * sj;
            sx[p][2][row] = si * cj;
            sx[p][3][row] = si * sj;
        } else {
            int j = it - NP * CTA_R;
            int p = j >> 7, col = j & (CTA_C - 1);
            float2 a = *(const float2*)(Y + (size_t)(bn + col) * NW + 2 * p);
            float si, ci, sj, cj;
            __sincosf(0.5f * a.x, &si, &ci);
            __sincosf(0.5f * a.y, &sj, &cj);
            sy[p][0][col] = ci * cj;
            sy[p][1][col] = ci * sj;
            sy[p][2][col] = si * cj;
            sy[p][3][col] = si * sj;
        }
    }
    __syncthreads();

    const int warp = tid >> 5;
    const int lane = tid & 31;
    const int r0 = warp * 4;              // warp-uniform 4-row block
    const int c0 = lane * 4;              // 4 consecutive cols per thread

    u64 acc[4][2];                        // [row][colpack]

#pragma unroll
    for (int p = 0; p < NP; ++p) {
        // y side: one conflict-free LDS.128 per quantity (4 cols = 2 packs)
        u64 y[NQ][2];
#pragma unroll
        for (int q = 0; q < NQ; ++q) {
            ulonglong2 v = *(const ulonglong2*)&sy[p][q][c0];
            y[q][0] = v.x; y[q][1] = v.y;
        }
        // x side: one broadcast LDS.128 per quantity (4 rows), dup via ALU movs
        float4 xv[NQ];
#pragma unroll
        for (int q = 0; q < NQ; ++q)
            xv[q] = *(const float4*)&sx[p][q][r0];
#pragma unroll
        for (int r = 0; r < 4; ++r) {
            const float* fx = (const float*)&xv[0];     // xv laid out contiguously
            u64 x0 = dup2(((const float4*)fx)[0].x), x1, x2, x3;
            // (explicit per-row component selection)
            float v0 = (r == 0) ? xv[0].x : (r == 1) ? xv[0].y : (r == 2) ? xv[0].z : xv[0].w;
            float v1 = (r == 0) ? xv[1].x : (r == 1) ? xv[1].y : (r == 2) ? xv[1].z : xv[1].w;
            float v2 = (r == 0) ? xv[2].x : (r == 1) ? xv[2].y : (r == 2) ? xv[2].z : xv[2].w;
            float v3 = (r == 0) ? xv[3].x : (r == 1) ? xv[3].y : (r == 2) ? xv[3].z : xv[3].w;
            x0 = dup2(v0); x1 = dup2(v1); x2 = dup2(v2); x3 = dup2(v3);
#pragma unroll
            for (int k = 0; k < 2; ++k) {
                u64 t = mul2(x0, y[0][k]);
                t = fma2(x1, y[1][k], t);
                t = fma2(x2, y[2][k], t);
                t = fma2(x3, y[3][k], t);
                acc[r][k] = (p == 0) ? t : mul2(acc[r][k], t);
            }
        }
    }

    // epilogue: square packed cols, one STG.128 per row
#pragma unroll
    for (int r = 0; r < 4; ++r) {
        ulonglong2 v;
        v.x = mul2(acc[r][0], acc[r][0]);
        v.y = mul2(acc[r][1], acc[r][1]);
        *(ulonglong2*)(out + (size_t)(bm + r0 + r) * NSAMP + bn + c0) = v;
    }
}

extern "C" void kernel_launch(void* const* d_in, const int* in_sizes, int n_in,
                              void* d_out, int out_size) {
    const float* X = (const float*)d_in[0];      // (4096, 10)
    const float* Y = (const float*)d_in[1];      // (4096, 10)
    // d_in[2] (params) provably does not affect the output (unitary invariance)
    float* out = (float*)d_out;                  // (4096, 4096)

    dim3 grid(NSAMP / CTA_C, NSAMP / CTA_R);     // (32, 128) = 4096 CTAs
    qk_kernel<<<grid, 256>>>(X, Y, out);
}